// round 3
// baseline (speedup 1.0000x reference)
#include <cuda_runtime.h>

#define NN 100000
#define EE 800000
#define HH 4
#define FI 64
#define FO 64

// ---------------- scratch (__device__ globals: no allocation allowed) ----------------
__device__ float g_h[(size_t)NN * 256];      // [N][H*O] transformed features
__device__ float g_local[(size_t)NN * 64];   // attention output (head-mean)
__device__ float g_g1[(size_t)NN * 64];      // hop-1 aggregate
__device__ float g_g2[(size_t)NN * 64];      // hop-2 aggregate
__device__ float g_ssrc[NN * 4];             // per-node src logits [N][H]
__device__ float g_sdst[NN * 4];             // per-node dst logits [N][H]
__device__ int   g_deg[NN];
__device__ int   g_offs[NN + 1];
__device__ int   g_cursor[NN];
__device__ int   g_csr[EE];                  // src node per CSR slot (sorted by dst)
__device__ float g_W2[64 * 64];              // W_g @ W_w[64:128]
__device__ float g_b2[64];                   // b_g @ W_w[64:128] + b_w
__device__ int   g_is64;                     // edge_index dtype flag

__device__ __forceinline__ float lrelu(float v) { return v > 0.f ? v : 0.2f * v; }

// ---------------- -1: detect edge_index dtype (int32 vs int64) ----------------
__global__ void k_detect(const unsigned int* __restrict__ w) {
    __shared__ int allzero;
    if (threadIdx.x == 0) allzero = 1;
    __syncthreads();
    for (int i = threadIdx.x; i < 1024; i += blockDim.x)
        if (w[2 * i + 1] != 0u) allzero = 0;
    __syncthreads();
    if (threadIdx.x == 0) g_is64 = allzero;
}

__device__ __forceinline__ int edge_at(const void* ei, int idx) {
    if (g_is64) return (int)((const long long*)ei)[idx];
    return ((const int*)ei)[idx];
}

// ---------------- 0: zero scratch ----------------
__global__ void k_init() {
    int i = blockIdx.x * blockDim.x + threadIdx.x;
    int st = gridDim.x * blockDim.x;
    for (int j = i; j < NN; j += st) g_deg[j] = 0;
    for (int j = i; j < NN * 4; j += st) { g_ssrc[j] = 0.f; g_sdst[j] = 0.f; }
}

// ---------------- 1: degree histogram ----------------
__global__ void k_hist(const void* __restrict__ ei) {
    int i = blockIdx.x * blockDim.x + threadIdx.x;
    int st = gridDim.x * blockDim.x;
    for (int e = i; e < EE; e += st) {
        int d = edge_at(ei, EE + e);
        atomicAdd(&g_deg[d], 1);
    }
}

// ---------------- 2: single-block exclusive scan -> offsets ----------------
__global__ void k_scan() {
    __shared__ int sm[1024];
    int tid = threadIdx.x;
    const int chunk = (NN + 1023) / 1024;
    int b = tid * chunk;
    int en = min(b + chunk, NN);
    int s = 0;
    for (int i = b; i < en; i++) s += g_deg[i];
    sm[tid] = s;
    __syncthreads();
    for (int off = 1; off < 1024; off <<= 1) {
        int v = (tid >= off) ? sm[tid - off] : 0;
        __syncthreads();
        sm[tid] += v;
        __syncthreads();
    }
    int run = (tid == 0) ? 0 : sm[tid - 1];
    for (int i = b; i < en; i++) {
        g_offs[i] = run;
        g_cursor[i] = run;
        run += g_deg[i];
    }
    if (tid == 1023) g_offs[NN] = sm[1023];
}

// ---------------- 3: scatter edges into CSR by dst ----------------
__global__ void k_scatter(const void* __restrict__ ei) {
    int i = blockIdx.x * blockDim.x + threadIdx.x;
    int st = gridDim.x * blockDim.x;
    for (int e = i; e < EE; e += st) {
        int s = edge_at(ei, e);
        int d = edge_at(ei, EE + e);
        int pos = atomicAdd(&g_cursor[d], 1);
        g_csr[pos] = s;
    }
}

// ---------------- 4: h = x @ W_att  +  per-node logits s_src/s_dst ----------------
#define FEAT_NPB 64
#define FEAT_BATCH 8
__global__ void __launch_bounds__(128) k_feat(const float* __restrict__ x,
                                              const float* __restrict__ W_att,
                                              const float* __restrict__ a_src,
                                              const float* __restrict__ a_dst) {
    __shared__ float xsh[FEAT_BATCH][64];
    int tid = threadIdx.x;
    int lane = tid & 31;
    int node0 = blockIdx.x * FEAT_NPB;

    for (int hp = 0; hp < 2; hp++) {
        int hh = hp * 2 + (tid >> 6);
        int o = tid & 63;
        float wcol[64];
        const float* wp = W_att + (size_t)hh * 64 * 64 + o;
#pragma unroll
        for (int k = 0; k < 64; k++) wcol[k] = wp[k * 64];
        float av_s = a_src[hh * 64 + o];
        float av_d = a_dst[hh * 64 + o];

        for (int nb = 0; nb < FEAT_NPB; nb += FEAT_BATCH) {
            __syncthreads();
            for (int i = tid; i < FEAT_BATCH * 64; i += 128) {
                int nn = node0 + nb + (i >> 6);
                xsh[i >> 6][i & 63] = (nn < NN) ? x[(size_t)nn * 64 + (i & 63)] : 0.f;
            }
            __syncthreads();
#pragma unroll 1
            for (int bb = 0; bb < FEAT_BATCH; bb++) {
                int n = node0 + nb + bb;
                if (n >= NN) break;
                const float4* xr = (const float4*)xsh[bb];
                float acc = 0.f;
#pragma unroll
                for (int kk = 0; kk < 16; kk++) {
                    float4 xv = xr[kk];
                    acc += xv.x * wcol[kk * 4 + 0];
                    acc += xv.y * wcol[kk * 4 + 1];
                    acc += xv.z * wcol[kk * 4 + 2];
                    acc += xv.w * wcol[kk * 4 + 3];
                }
                g_h[(size_t)n * 256 + hp * 128 + tid] = acc;
                float vs = acc * av_s;
                float vd = acc * av_d;
#pragma unroll
                for (int off = 16; off; off >>= 1) {
                    vs += __shfl_xor_sync(0xFFFFFFFFu, vs, off);
                    vd += __shfl_xor_sync(0xFFFFFFFFu, vd, off);
                }
                if (lane == 0) {
                    atomicAdd(&g_ssrc[n * 4 + hh], vs);
                    atomicAdd(&g_sdst[n * 4 + hh], vd);
                }
            }
        }
    }
}

// ---------------- 5: attention — warp per destination node, atomic-free ----------------
__global__ void __launch_bounds__(256) k_attn() {
    int gw = (blockIdx.x * blockDim.x + threadIdx.x) >> 5;
    int lane = threadIdx.x & 31;
    if (gw >= NN) return;
    int n = gw;
    int beg = g_offs[n], end = g_offs[n + 1];
    float4 sd = *(const float4*)&g_sdst[n * 4];

    float m0 = -1e30f, m1 = -1e30f, m2 = -1e30f, m3 = -1e30f;
    for (int j = beg + lane; j < end; j += 32) {
        int s = g_csr[j];
        float4 ss = *(const float4*)&g_ssrc[s * 4];
        m0 = fmaxf(m0, lrelu(ss.x + sd.x));
        m1 = fmaxf(m1, lrelu(ss.y + sd.y));
        m2 = fmaxf(m2, lrelu(ss.z + sd.z));
        m3 = fmaxf(m3, lrelu(ss.w + sd.w));
    }
#pragma unroll
    for (int off = 16; off; off >>= 1) {
        m0 = fmaxf(m0, __shfl_xor_sync(0xFFFFFFFFu, m0, off));
        m1 = fmaxf(m1, __shfl_xor_sync(0xFFFFFFFFu, m1, off));
        m2 = fmaxf(m2, __shfl_xor_sync(0xFFFFFFFFu, m2, off));
        m3 = fmaxf(m3, __shfl_xor_sync(0xFFFFFFFFu, m3, off));
    }

    float d0 = 0.f, d1 = 0.f, d2 = 0.f, d3 = 0.f;
    for (int j = beg + lane; j < end; j += 32) {
        int s = g_csr[j];
        float4 ss = *(const float4*)&g_ssrc[s * 4];
        d0 += __expf(lrelu(ss.x + sd.x) - m0);
        d1 += __expf(lrelu(ss.y + sd.y) - m1);
        d2 += __expf(lrelu(ss.z + sd.z) - m2);
        d3 += __expf(lrelu(ss.w + sd.w) - m3);
    }
#pragma unroll
    for (int off = 16; off; off >>= 1) {
        d0 += __shfl_xor_sync(0xFFFFFFFFu, d0, off);
        d1 += __shfl_xor_sync(0xFFFFFFFFu, d1, off);
        d2 += __shfl_xor_sync(0xFFFFFFFFu, d2, off);
        d3 += __shfl_xor_sync(0xFFFFFFFFu, d3, off);
    }
    float i0 = 1.f / fmaxf(d0, 1e-16f);
    float i1 = 1.f / fmaxf(d1, 1e-16f);
    float i2 = 1.f / fmaxf(d2, 1e-16f);
    float i3 = 1.f / fmaxf(d3, 1e-16f);

    float a0 = 0.f, a1 = 0.f, a2 = 0.f, a3 = 0.f, a4 = 0.f, a5 = 0.f, a6 = 0.f, a7 = 0.f;
    for (int j = beg; j < end; j++) {
        int s = g_csr[j];
        float4 ss = *(const float4*)&g_ssrc[s * 4];
        float w0 = __expf(lrelu(ss.x + sd.x) - m0) * i0;
        float w1 = __expf(lrelu(ss.y + sd.y) - m1) * i1;
        float w2 = __expf(lrelu(ss.z + sd.z) - m2) * i2;
        float w3 = __expf(lrelu(ss.w + sd.w) - m3) * i3;
        const float* hr = g_h + (size_t)s * 256;
        a0 += w0 * hr[lane];
        a1 += w0 * hr[32 + lane];
        a2 += w1 * hr[64 + lane];
        a3 += w1 * hr[96 + lane];
        a4 += w2 * hr[128 + lane];
        a5 += w2 * hr[160 + lane];
        a6 += w3 * hr[192 + lane];
        a7 += w3 * hr[224 + lane];
    }
    g_local[(size_t)n * 64 + lane]      = 0.25f * (a0 + a2 + a4 + a6);
    g_local[(size_t)n * 64 + 32 + lane] = 0.25f * (a1 + a3 + a5 + a7);
}

// ---------------- 6: hop aggregation — device symbols bound INSIDE the kernel ----------------
// (Passing __device__ symbols from host passes the host shadow address; on GB300
//  ATS makes those writes silently land in host memory. Bind symbols in-kernel.)
__global__ void __launch_bounds__(256) k_glob1(const float* __restrict__ x) {
    int gw = (blockIdx.x * blockDim.x + threadIdx.x) >> 5;
    int lane = threadIdx.x & 31;
    if (gw >= NN) return;
    int n = gw;
    int beg = g_offs[n], end = g_offs[n + 1];
    float a0 = 0.f, a1 = 0.f;
    for (int j = beg; j < end; j++) {
        int s = g_csr[j];
        const float* r = x + (size_t)s * 64;
        a0 += r[lane];
        a1 += r[32 + lane];
    }
    float inv = 1.f / fmaxf((float)(end - beg), 1.f);
    g_g1[(size_t)n * 64 + lane] = a0 * inv;
    g_g1[(size_t)n * 64 + 32 + lane] = a1 * inv;
}

__global__ void __launch_bounds__(256) k_glob2() {
    int gw = (blockIdx.x * blockDim.x + threadIdx.x) >> 5;
    int lane = threadIdx.x & 31;
    if (gw >= NN) return;
    int n = gw;
    int beg = g_offs[n], end = g_offs[n + 1];
    float a0 = 0.f, a1 = 0.f;
    for (int j = beg; j < end; j++) {
        int s = g_csr[j];
        const float* r = g_g1 + (size_t)s * 64;
        a0 += r[lane];
        a1 += r[32 + lane];
    }
    float inv = 1.f / fmaxf((float)(end - beg), 1.f);
    g_g2[(size_t)n * 64 + lane] = a0 * inv;
    g_g2[(size_t)n * 64 + 32 + lane] = a1 * inv;
}

// ---------------- 7: fold W_g into W_w lower half: W2 = W_g @ W_w[64:], b2 ----------------
__global__ void k_wg(const float* __restrict__ W_g, const float* __restrict__ b_g,
                     const float* __restrict__ W_w, const float* __restrict__ b_w) {
    int i0 = blockIdx.x * blockDim.x + threadIdx.x;
    int st = gridDim.x * blockDim.x;
    for (int idx = i0; idx < 4096; idx += st) {
        int i = idx >> 6, o = idx & 63;
        float s = 0.f;
        for (int k = 0; k < 64; k++)
            s += W_g[i * 64 + k] * W_w[(64 + k) * 64 + o];
        g_W2[idx] = s;
    }
    for (int o = i0; o < 64; o += st) {
        float s = b_w[o];
        for (int k = 0; k < 64; k++)
            s += b_g[k] * W_w[(64 + k) * 64 + o];
        g_b2[o] = s;
    }
}

// ---------------- 8: final projection out = local@W1 + g2@W2 + b2 ----------------
#define FIN_NPB 64
__global__ void __launch_bounds__(256) k_final(const float* __restrict__ W_w,
                                               float* __restrict__ out) {
    __shared__ float W1s[4096];
    __shared__ float W2s[4096];
    __shared__ float bs[64];
    __shared__ float ls[4][64];
    __shared__ float gs[4][64];
    int tid = threadIdx.x;
    for (int i = tid; i < 4096; i += 256) {
        W1s[i] = W_w[i];
        W2s[i] = g_W2[i];
    }
    if (tid < 64) bs[tid] = g_b2[tid];
    __syncthreads();

    int node0 = blockIdx.x * FIN_NPB;
    for (int nb = 0; nb < FIN_NPB; nb += 4) {
        __syncthreads();
        {
            int nn = node0 + nb + (tid >> 6);
            int c = tid & 63;
            if (nn < NN) {
                ls[tid >> 6][c] = g_local[(size_t)nn * 64 + c];
                gs[tid >> 6][c] = g_g2[(size_t)nn * 64 + c];
            }
        }
        __syncthreads();
        int nn = node0 + nb + (tid >> 6);
        if (nn < NN) {
            int o = tid & 63;
            float acc = bs[o];
            const float4* lr = (const float4*)ls[tid >> 6];
            const float4* gr = (const float4*)gs[tid >> 6];
#pragma unroll
            for (int kk = 0; kk < 16; kk++) {
                float4 lv = lr[kk];
                float4 gv = gr[kk];
                acc += lv.x * W1s[(kk * 4 + 0) * 64 + o] + gv.x * W2s[(kk * 4 + 0) * 64 + o];
                acc += lv.y * W1s[(kk * 4 + 1) * 64 + o] + gv.y * W2s[(kk * 4 + 1) * 64 + o];
                acc += lv.z * W1s[(kk * 4 + 2) * 64 + o] + gv.z * W2s[(kk * 4 + 2) * 64 + o];
                acc += lv.w * W1s[(kk * 4 + 3) * 64 + o] + gv.w * W2s[(kk * 4 + 3) * 64 + o];
            }
            out[(size_t)nn * 64 + o] = acc;
        }
    }
}

// ---------------- launch ----------------
extern "C" void kernel_launch(void* const* d_in, const int* in_sizes, int n_in,
                              void* d_out, int out_size) {
    const float* x     = (const float*)d_in[0];
    const void*  ei    = d_in[1];
    const float* W_att = (const float*)d_in[2];
    const float* a_src = (const float*)d_in[3];
    const float* a_dst = (const float*)d_in[4];
    const float* W_g   = (const float*)d_in[5];
    const float* b_g   = (const float*)d_in[6];
    const float* W_w   = (const float*)d_in[7];
    const float* b_w   = (const float*)d_in[8];
    float* out = (float*)d_out;

    k_detect<<<1, 256>>>((const unsigned int*)ei);
    k_init<<<256, 256>>>();
    k_hist<<<3125, 256>>>(ei);
    k_scan<<<1, 1024>>>();
    k_scatter<<<3125, 256>>>(ei);
    k_feat<<<(NN + FEAT_NPB - 1) / FEAT_NPB, 128>>>(x, W_att, a_src, a_dst);
    k_attn<<<(NN * 32 + 255) / 256, 256>>>();
    k_glob1<<<(NN * 32 + 255) / 256, 256>>>(x);
    k_glob2<<<(NN * 32 + 255) / 256, 256>>>();
    k_wg<<<17, 256>>>(W_g, b_g, W_w, b_w);
    k_final<<<(NN + FIN_NPB - 1) / FIN_NPB, 256>>>(W_w, out);
}

// round 4
// speedup vs baseline: 1.2545x; 1.2545x over previous
#include <cuda_runtime.h>

#define NN 100000
#define EE 800000
#define HH 4
#define FI 64
#define FO 64
#define SCAN_BLKS ((NN + 1023) / 1024)   // 98

// ---------------- scratch (__device__ globals: no allocation allowed) ----------------
__device__ float g_h[(size_t)NN * 256];      // [N][H*O] transformed features
__device__ float g_local[(size_t)NN * 64];   // attention output (head-mean)
__device__ float g_g1[(size_t)NN * 64];      // hop-1 aggregate
__device__ float g_g2[(size_t)NN * 64];      // hop-2 aggregate
__device__ float g_ssrc[NN * 4];             // per-node src logits [N][H]
__device__ float g_sdst[NN * 4];             // per-node dst logits [N][H]
__device__ int   g_deg[NN];
__device__ int   g_offs[NN + 1];
__device__ int   g_cursor[NN];
__device__ int   g_csr[EE];                  // src node per CSR slot (sorted by dst)
__device__ float g_W2[64 * 64];              // W_g @ W_w[64:128]
__device__ float g_b2[64];                   // b_g @ W_w[64:128] + b_w
__device__ int   g_is64;                     // edge_index dtype flag
__device__ int   g_bsum[SCAN_BLKS];          // per-block degree totals
__device__ int   g_bbase[SCAN_BLKS];         // exclusive prefix of block totals

__device__ __forceinline__ float lrelu(float v) { return v > 0.f ? v : 0.2f * v; }

// ---------------- -1: detect edge_index dtype (int32 vs int64) ----------------
__global__ void k_detect(const unsigned int* __restrict__ w) {
    __shared__ int allzero;
    if (threadIdx.x == 0) allzero = 1;
    __syncthreads();
    for (int i = threadIdx.x; i < 1024; i += blockDim.x)
        if (w[2 * i + 1] != 0u) allzero = 0;
    __syncthreads();
    if (threadIdx.x == 0) g_is64 = allzero;
}

__device__ __forceinline__ int edge_at(const void* ei, int idx) {
    if (g_is64) return (int)((const long long*)ei)[idx];
    return ((const int*)ei)[idx];
}

// ---------------- 0: zero scratch ----------------
__global__ void k_init() {
    int i = blockIdx.x * blockDim.x + threadIdx.x;
    int st = gridDim.x * blockDim.x;
    for (int j = i; j < NN; j += st) g_deg[j] = 0;
    for (int j = i; j < NN * 4; j += st) { g_ssrc[j] = 0.f; g_sdst[j] = 0.f; }
}

// ---------------- 1: degree histogram ----------------
__global__ void k_hist(const void* __restrict__ ei) {
    int i = blockIdx.x * blockDim.x + threadIdx.x;
    int st = gridDim.x * blockDim.x;
    for (int e = i; e < EE; e += st) {
        int d = edge_at(ei, EE + e);
        atomicAdd(&g_deg[d], 1);
    }
}

// ---------------- 2: device-wide exclusive scan of g_deg (3 phases) ----------------
__global__ void __launch_bounds__(1024) k_scan_a() {
    __shared__ int sm[1024];
    int tid = threadIdx.x;
    int gid = blockIdx.x * 1024 + tid;
    int v = (gid < NN) ? g_deg[gid] : 0;
    sm[tid] = v;
    __syncthreads();
#pragma unroll
    for (int off = 1; off < 1024; off <<= 1) {
        int t = (tid >= off) ? sm[tid - off] : 0;
        __syncthreads();
        sm[tid] += t;
        __syncthreads();
    }
    if (gid < NN) g_offs[gid] = sm[tid] - v;       // local exclusive prefix
    if (tid == 1023) g_bsum[blockIdx.x] = sm[1023];
}

__global__ void __launch_bounds__(128) k_scan_b() {
    __shared__ int sm[128];
    int tid = threadIdx.x;
    int v = (tid < SCAN_BLKS) ? g_bsum[tid] : 0;
    sm[tid] = v;
    __syncthreads();
#pragma unroll
    for (int off = 1; off < 128; off <<= 1) {
        int t = (tid >= off) ? sm[tid - off] : 0;
        __syncthreads();
        sm[tid] += t;
        __syncthreads();
    }
    if (tid < SCAN_BLKS) g_bbase[tid] = sm[tid] - v;
    if (tid == 127) g_offs[NN] = sm[127];          // total == EE
}

__global__ void __launch_bounds__(1024) k_scan_c() {
    int gid = blockIdx.x * 1024 + threadIdx.x;
    if (gid < NN) {
        int o = g_offs[gid] + g_bbase[blockIdx.x];
        g_offs[gid] = o;
        g_cursor[gid] = o;
    }
}

// ---------------- 3: scatter edges into CSR by dst ----------------
__global__ void k_scatter(const void* __restrict__ ei) {
    int i = blockIdx.x * blockDim.x + threadIdx.x;
    int st = gridDim.x * blockDim.x;
    for (int e = i; e < EE; e += st) {
        int s = edge_at(ei, e);
        int d = edge_at(ei, EE + e);
        int pos = atomicAdd(&g_cursor[d], 1);
        g_csr[pos] = s;
    }
}

// ---------------- 4: h = x @ W_att  +  per-node logits s_src/s_dst ----------------
#define FEAT_NPB 64
#define FEAT_BATCH 8
__global__ void __launch_bounds__(128) k_feat(const float* __restrict__ x,
                                              const float* __restrict__ W_att,
                                              const float* __restrict__ a_src,
                                              const float* __restrict__ a_dst) {
    __shared__ float xsh[FEAT_BATCH][64];
    int tid = threadIdx.x;
    int lane = tid & 31;
    int node0 = blockIdx.x * FEAT_NPB;

    for (int hp = 0; hp < 2; hp++) {
        int hh = hp * 2 + (tid >> 6);
        int o = tid & 63;
        float wcol[64];
        const float* wp = W_att + (size_t)hh * 64 * 64 + o;
#pragma unroll
        for (int k = 0; k < 64; k++) wcol[k] = wp[k * 64];
        float av_s = a_src[hh * 64 + o];
        float av_d = a_dst[hh * 64 + o];

        for (int nb = 0; nb < FEAT_NPB; nb += FEAT_BATCH) {
            __syncthreads();
            for (int i = tid; i < FEAT_BATCH * 64; i += 128) {
                int nn = node0 + nb + (i >> 6);
                xsh[i >> 6][i & 63] = (nn < NN) ? x[(size_t)nn * 64 + (i & 63)] : 0.f;
            }
            __syncthreads();
#pragma unroll 1
            for (int bb = 0; bb < FEAT_BATCH; bb++) {
                int n = node0 + nb + bb;
                if (n >= NN) break;
                const float4* xr = (const float4*)xsh[bb];
                float acc = 0.f;
#pragma unroll
                for (int kk = 0; kk < 16; kk++) {
                    float4 xv = xr[kk];
                    acc += xv.x * wcol[kk * 4 + 0];
                    acc += xv.y * wcol[kk * 4 + 1];
                    acc += xv.z * wcol[kk * 4 + 2];
                    acc += xv.w * wcol[kk * 4 + 3];
                }
                g_h[(size_t)n * 256 + hp * 128 + tid] = acc;
                float vs = acc * av_s;
                float vd = acc * av_d;
#pragma unroll
                for (int off = 16; off; off >>= 1) {
                    vs += __shfl_xor_sync(0xFFFFFFFFu, vs, off);
                    vd += __shfl_xor_sync(0xFFFFFFFFu, vd, off);
                }
                if (lane == 0) {
                    atomicAdd(&g_ssrc[n * 4 + hh], vs);
                    atomicAdd(&g_sdst[n * 4 + hh], vd);
                }
            }
        }
    }
}

// ---------------- 5: attention — warp per destination node, atomic-free ----------------
__global__ void __launch_bounds__(256) k_attn() {
    int gw = (blockIdx.x * blockDim.x + threadIdx.x) >> 5;
    int lane = threadIdx.x & 31;
    if (gw >= NN) return;
    int n = gw;
    int beg = g_offs[n], end = g_offs[n + 1];
    float4 sd = *(const float4*)&g_sdst[n * 4];

    float m0 = -1e30f, m1 = -1e30f, m2 = -1e30f, m3 = -1e30f;
    for (int j = beg + lane; j < end; j += 32) {
        int s = g_csr[j];
        float4 ss = *(const float4*)&g_ssrc[s * 4];
        m0 = fmaxf(m0, lrelu(ss.x + sd.x));
        m1 = fmaxf(m1, lrelu(ss.y + sd.y));
        m2 = fmaxf(m2, lrelu(ss.z + sd.z));
        m3 = fmaxf(m3, lrelu(ss.w + sd.w));
    }
#pragma unroll
    for (int off = 16; off; off >>= 1) {
        m0 = fmaxf(m0, __shfl_xor_sync(0xFFFFFFFFu, m0, off));
        m1 = fmaxf(m1, __shfl_xor_sync(0xFFFFFFFFu, m1, off));
        m2 = fmaxf(m2, __shfl_xor_sync(0xFFFFFFFFu, m2, off));
        m3 = fmaxf(m3, __shfl_xor_sync(0xFFFFFFFFu, m3, off));
    }

    float d0 = 0.f, d1 = 0.f, d2 = 0.f, d3 = 0.f;
    for (int j = beg + lane; j < end; j += 32) {
        int s = g_csr[j];
        float4 ss = *(const float4*)&g_ssrc[s * 4];
        d0 += __expf(lrelu(ss.x + sd.x) - m0);
        d1 += __expf(lrelu(ss.y + sd.y) - m1);
        d2 += __expf(lrelu(ss.z + sd.z) - m2);
        d3 += __expf(lrelu(ss.w + sd.w) - m3);
    }
#pragma unroll
    for (int off = 16; off; off >>= 1) {
        d0 += __shfl_xor_sync(0xFFFFFFFFu, d0, off);
        d1 += __shfl_xor_sync(0xFFFFFFFFu, d1, off);
        d2 += __shfl_xor_sync(0xFFFFFFFFu, d2, off);
        d3 += __shfl_xor_sync(0xFFFFFFFFu, d3, off);
    }
    float i0 = 1.f / fmaxf(d0, 1e-16f);
    float i1 = 1.f / fmaxf(d1, 1e-16f);
    float i2 = 1.f / fmaxf(d2, 1e-16f);
    float i3 = 1.f / fmaxf(d3, 1e-16f);

    float a0 = 0.f, a1 = 0.f, a2 = 0.f, a3 = 0.f, a4 = 0.f, a5 = 0.f, a6 = 0.f, a7 = 0.f;
    for (int j = beg; j < end; j++) {
        int s = g_csr[j];
        float4 ss = *(const float4*)&g_ssrc[s * 4];
        float w0 = __expf(lrelu(ss.x + sd.x) - m0) * i0;
        float w1 = __expf(lrelu(ss.y + sd.y) - m1) * i1;
        float w2 = __expf(lrelu(ss.z + sd.z) - m2) * i2;
        float w3 = __expf(lrelu(ss.w + sd.w) - m3) * i3;
        const float* hr = g_h + (size_t)s * 256;
        a0 += w0 * hr[lane];
        a1 += w0 * hr[32 + lane];
        a2 += w1 * hr[64 + lane];
        a3 += w1 * hr[96 + lane];
        a4 += w2 * hr[128 + lane];
        a5 += w2 * hr[160 + lane];
        a6 += w3 * hr[192 + lane];
        a7 += w3 * hr[224 + lane];
    }
    g_local[(size_t)n * 64 + lane]      = 0.25f * (a0 + a2 + a4 + a6);
    g_local[(size_t)n * 64 + 32 + lane] = 0.25f * (a1 + a3 + a5 + a7);
}

// ---------------- 6: hop aggregation — device symbols bound INSIDE the kernel ----------------
__global__ void __launch_bounds__(256) k_glob1(const float* __restrict__ x) {
    int gw = (blockIdx.x * blockDim.x + threadIdx.x) >> 5;
    int lane = threadIdx.x & 31;
    if (gw >= NN) return;
    int n = gw;
    int beg = g_offs[n], end = g_offs[n + 1];
    float a0 = 0.f, a1 = 0.f;
    for (int j = beg; j < end; j++) {
        int s = g_csr[j];
        const float* r = x + (size_t)s * 64;
        a0 += r[lane];
        a1 += r[32 + lane];
    }
    float inv = 1.f / fmaxf((float)(end - beg), 1.f);
    g_g1[(size_t)n * 64 + lane] = a0 * inv;
    g_g1[(size_t)n * 64 + 32 + lane] = a1 * inv;
}

__global__ void __launch_bounds__(256) k_glob2() {
    int gw = (blockIdx.x * blockDim.x + threadIdx.x) >> 5;
    int lane = threadIdx.x & 31;
    if (gw >= NN) return;
    int n = gw;
    int beg = g_offs[n], end = g_offs[n + 1];
    float a0 = 0.f, a1 = 0.f;
    for (int j = beg; j < end; j++) {
        int s = g_csr[j];
        const float* r = g_g1 + (size_t)s * 64;
        a0 += r[lane];
        a1 += r[32 + lane];
    }
    float inv = 1.f / fmaxf((float)(end - beg), 1.f);
    g_g2[(size_t)n * 64 + lane] = a0 * inv;
    g_g2[(size_t)n * 64 + 32 + lane] = a1 * inv;
}

// ---------------- 7: fold W_g into W_w lower half: W2 = W_g @ W_w[64:], b2 ----------------
__global__ void k_wg(const float* __restrict__ W_g, const float* __restrict__ b_g,
                     const float* __restrict__ W_w, const float* __restrict__ b_w) {
    int i0 = blockIdx.x * blockDim.x + threadIdx.x;
    int st = gridDim.x * blockDim.x;
    for (int idx = i0; idx < 4096; idx += st) {
        int i = idx >> 6, o = idx & 63;
        float s = 0.f;
        for (int k = 0; k < 64; k++)
            s += W_g[i * 64 + k] * W_w[(64 + k) * 64 + o];
        g_W2[idx] = s;
    }
    for (int o = i0; o < 64; o += st) {
        float s = b_w[o];
        for (int k = 0; k < 64; k++)
            s += b_g[k] * W_w[(64 + k) * 64 + o];
        g_b2[o] = s;
    }
}

// ---------------- 8: final projection out = local@W1 + g2@W2 + b2 ----------------
#define FIN_NPB 64
__global__ void __launch_bounds__(256) k_final(const float* __restrict__ W_w,
                                               float* __restrict__ out) {
    __shared__ float W1s[4096];
    __shared__ float W2s[4096];
    __shared__ float bs[64];
    __shared__ float ls[4][64];
    __shared__ float gs[4][64];
    int tid = threadIdx.x;
    for (int i = tid; i < 4096; i += 256) {
        W1s[i] = W_w[i];
        W2s[i] = g_W2[i];
    }
    if (tid < 64) bs[tid] = g_b2[tid];
    __syncthreads();

    int node0 = blockIdx.x * FIN_NPB;
    for (int nb = 0; nb < FIN_NPB; nb += 4) {
        __syncthreads();
        {
            int nn = node0 + nb + (tid >> 6);
            int c = tid & 63;
            if (nn < NN) {
                ls[tid >> 6][c] = g_local[(size_t)nn * 64 + c];
                gs[tid >> 6][c] = g_g2[(size_t)nn * 64 + c];
            }
        }
        __syncthreads();
        int nn = node0 + nb + (tid >> 6);
        if (nn < NN) {
            int o = tid & 63;
            float acc = bs[o];
            const float4* lr = (const float4*)ls[tid >> 6];
            const float4* gr = (const float4*)gs[tid >> 6];
#pragma unroll
            for (int kk = 0; kk < 16; kk++) {
                float4 lv = lr[kk];
                float4 gv = gr[kk];
                acc += lv.x * W1s[(kk * 4 + 0) * 64 + o] + gv.x * W2s[(kk * 4 + 0) * 64 + o];
                acc += lv.y * W1s[(kk * 4 + 1) * 64 + o] + gv.y * W2s[(kk * 4 + 1) * 64 + o];
                acc += lv.z * W1s[(kk * 4 + 2) * 64 + o] + gv.z * W2s[(kk * 4 + 2) * 64 + o];
                acc += lv.w * W1s[(kk * 4 + 3) * 64 + o] + gv.w * W2s[(kk * 4 + 3) * 64 + o];
            }
            out[(size_t)nn * 64 + o] = acc;
        }
    }
}

// ---------------- launch ----------------
extern "C" void kernel_launch(void* const* d_in, const int* in_sizes, int n_in,
                              void* d_out, int out_size) {
    const float* x     = (const float*)d_in[0];
    const void*  ei    = d_in[1];
    const float* W_att = (const float*)d_in[2];
    const float* a_src = (const float*)d_in[3];
    const float* a_dst = (const float*)d_in[4];
    const float* W_g   = (const float*)d_in[5];
    const float* b_g   = (const float*)d_in[6];
    const float* W_w   = (const float*)d_in[7];
    const float* b_w   = (const float*)d_in[8];
    float* out = (float*)d_out;

    k_detect<<<1, 256>>>((const unsigned int*)ei);
    k_init<<<256, 256>>>();
    k_hist<<<3125, 256>>>(ei);
    k_scan_a<<<SCAN_BLKS, 1024>>>();
    k_scan_b<<<1, 128>>>();
    k_scan_c<<<SCAN_BLKS, 1024>>>();
    k_scatter<<<3125, 256>>>(ei);
    k_feat<<<(NN + FEAT_NPB - 1) / FEAT_NPB, 128>>>(x, W_att, a_src, a_dst);
    k_attn<<<(NN * 32 + 255) / 256, 256>>>();
    k_glob1<<<(NN * 32 + 255) / 256, 256>>>(x);
    k_glob2<<<(NN * 32 + 255) / 256, 256>>>();
    k_wg<<<17, 256>>>(W_g, b_g, W_w, b_w);
    k_final<<<(NN + FIN_NPB - 1) / FIN_NPB, 256>>>(W_w, out);
}

// round 5
// speedup vs baseline: 1.4206x; 1.1324x over previous
#include <cuda_runtime.h>
#include <cuda_fp16.h>

#define NN 100000
#define EE 800000
#define SCAN_BLKS ((NN + 1023) / 1024)   // 98

// ---------------- scratch (__device__ globals: no allocation allowed) ----------------
__device__ __align__(16) __half g_h[(size_t)NN * 256];   // [N][H*64] transformed feats (fp16)
__device__ __align__(16) __half g_xh[(size_t)NN * 64];   // fp16 copy of x
__device__ __align__(16) __half g_g1h[(size_t)NN * 64];  // hop-1 aggregate (fp16)
__device__ float g_local[(size_t)NN * 64];   // attention output (head-mean)
__device__ float g_g2[(size_t)NN * 64];      // hop-2 aggregate
__device__ __align__(16) float g_ssrc[NN * 4];           // per-node src logits [N][H]
__device__ __align__(16) float g_sdst[NN * 4];           // per-node dst logits [N][H]
__device__ int   g_deg[NN];
__device__ int   g_offs[NN + 1];
__device__ int   g_cursor[NN];
__device__ int   g_csr[EE];                  // src node per CSR slot (sorted by dst)
__device__ float g_W2[64 * 64];              // W_g @ W_w[64:128]
__device__ float g_b2[64];                   // b_g @ W_w[64:128] + b_w
__device__ int   g_is64;                     // edge_index dtype flag
__device__ int   g_bsum[SCAN_BLKS];
__device__ int   g_bbase[SCAN_BLKS];

__device__ __forceinline__ float lrelu(float v) { return v > 0.f ? v : 0.2f * v; }

// ---------------- -1: detect edge_index dtype (int32 vs int64) ----------------
__global__ void k_detect(const unsigned int* __restrict__ w) {
    __shared__ int allzero;
    if (threadIdx.x == 0) allzero = 1;
    __syncthreads();
    for (int i = threadIdx.x; i < 1024; i += blockDim.x)
        if (w[2 * i + 1] != 0u) allzero = 0;
    __syncthreads();
    if (threadIdx.x == 0) g_is64 = allzero;
}

__device__ __forceinline__ int edge_at(const void* ei, int idx) {
    if (g_is64) return (int)((const long long*)ei)[idx];
    return ((const int*)ei)[idx];
}

// ---------------- 0: zero scratch + fp16 copy of x ----------------
__global__ void k_init(const float* __restrict__ x) {
    int i = blockIdx.x * blockDim.x + threadIdx.x;
    int st = gridDim.x * blockDim.x;
    for (int j = i; j < NN; j += st) g_deg[j] = 0;
    for (int j = i; j < NN * 4; j += st) { g_ssrc[j] = 0.f; g_sdst[j] = 0.f; }
    // x -> fp16 (as half2 pairs)
    const float2* x2 = (const float2*)x;
    __half2* xh2 = (__half2*)g_xh;
    for (int j = i; j < NN * 32; j += st) {
        float2 v = x2[j];
        xh2[j] = __floats2half2_rn(v.x, v.y);
    }
}

// ---------------- 1: degree histogram ----------------
__global__ void k_hist(const void* __restrict__ ei) {
    int i = blockIdx.x * blockDim.x + threadIdx.x;
    int st = gridDim.x * blockDim.x;
    for (int e = i; e < EE; e += st) {
        int d = edge_at(ei, EE + e);
        atomicAdd(&g_deg[d], 1);
    }
}

// ---------------- 2: device-wide exclusive scan of g_deg (3 phases) ----------------
__global__ void __launch_bounds__(1024) k_scan_a() {
    __shared__ int sm[1024];
    int tid = threadIdx.x;
    int gid = blockIdx.x * 1024 + tid;
    int v = (gid < NN) ? g_deg[gid] : 0;
    sm[tid] = v;
    __syncthreads();
#pragma unroll
    for (int off = 1; off < 1024; off <<= 1) {
        int t = (tid >= off) ? sm[tid - off] : 0;
        __syncthreads();
        sm[tid] += t;
        __syncthreads();
    }
    if (gid < NN) g_offs[gid] = sm[tid] - v;
    if (tid == 1023) g_bsum[blockIdx.x] = sm[1023];
}

__global__ void __launch_bounds__(128) k_scan_b() {
    __shared__ int sm[128];
    int tid = threadIdx.x;
    int v = (tid < SCAN_BLKS) ? g_bsum[tid] : 0;
    sm[tid] = v;
    __syncthreads();
#pragma unroll
    for (int off = 1; off < 128; off <<= 1) {
        int t = (tid >= off) ? sm[tid - off] : 0;
        __syncthreads();
        sm[tid] += t;
        __syncthreads();
    }
    if (tid < SCAN_BLKS) g_bbase[tid] = sm[tid] - v;
    if (tid == 127) g_offs[NN] = sm[127];
}

__global__ void __launch_bounds__(1024) k_scan_c() {
    int gid = blockIdx.x * 1024 + threadIdx.x;
    if (gid < NN) {
        int o = g_offs[gid] + g_bbase[blockIdx.x];
        g_offs[gid] = o;
        g_cursor[gid] = o;
    }
}

// ---------------- 3: scatter edges into CSR by dst ----------------
__global__ void k_scatter(const void* __restrict__ ei) {
    int i = blockIdx.x * blockDim.x + threadIdx.x;
    int st = gridDim.x * blockDim.x;
    for (int e = i; e < EE; e += st) {
        int s = edge_at(ei, e);
        int d = edge_at(ei, EE + e);
        int pos = atomicAdd(&g_cursor[d], 1);
        g_csr[pos] = s;
    }
}

// ---------------- 4: h = x @ W_att (fp32 math, fp16 store) + logits ----------------
#define FEAT_NPB 64
#define FEAT_BATCH 8
__global__ void __launch_bounds__(128) k_feat(const float* __restrict__ x,
                                              const float* __restrict__ W_att,
                                              const float* __restrict__ a_src,
                                              const float* __restrict__ a_dst) {
    __shared__ float xsh[FEAT_BATCH][64];
    int tid = threadIdx.x;
    int lane = tid & 31;
    int node0 = blockIdx.x * FEAT_NPB;

    for (int hp = 0; hp < 2; hp++) {
        int hh = hp * 2 + (tid >> 6);
        int o = tid & 63;
        float wcol[64];
        const float* wp = W_att + (size_t)hh * 64 * 64 + o;
#pragma unroll
        for (int k = 0; k < 64; k++) wcol[k] = wp[k * 64];
        float av_s = a_src[hh * 64 + o];
        float av_d = a_dst[hh * 64 + o];

        for (int nb = 0; nb < FEAT_NPB; nb += FEAT_BATCH) {
            __syncthreads();
            for (int i = tid; i < FEAT_BATCH * 64; i += 128) {
                int nn = node0 + nb + (i >> 6);
                xsh[i >> 6][i & 63] = (nn < NN) ? x[(size_t)nn * 64 + (i & 63)] : 0.f;
            }
            __syncthreads();
#pragma unroll 1
            for (int bb = 0; bb < FEAT_BATCH; bb++) {
                int n = node0 + nb + bb;
                if (n >= NN) break;
                const float4* xr = (const float4*)xsh[bb];
                float acc = 0.f;
#pragma unroll
                for (int kk = 0; kk < 16; kk++) {
                    float4 xv = xr[kk];
                    acc += xv.x * wcol[kk * 4 + 0];
                    acc += xv.y * wcol[kk * 4 + 1];
                    acc += xv.z * wcol[kk * 4 + 2];
                    acc += xv.w * wcol[kk * 4 + 3];
                }
                g_h[(size_t)n * 256 + hp * 128 + tid] = __float2half_rn(acc);
                float vs = acc * av_s;
                float vd = acc * av_d;
#pragma unroll
                for (int off = 16; off; off >>= 1) {
                    vs += __shfl_xor_sync(0xFFFFFFFFu, vs, off);
                    vd += __shfl_xor_sync(0xFFFFFFFFu, vd, off);
                }
                if (lane == 0) {
                    atomicAdd(&g_ssrc[n * 4 + hh], vs);
                    atomicAdd(&g_sdst[n * 4 + hh], vd);
                }
            }
        }
    }
}

// ---------------- 5: attention + hop-1, fused, warp per destination node ----------------
// Lane l owns 8 halves of the h-row (uint4); head = l>>3 fixed per lane.
// Softmax done as (sum exp*h)/(sum exp); per-head max pre-pass kept for stability.
__global__ void __launch_bounds__(256) k_attn() {
    int gw = (blockIdx.x * blockDim.x + threadIdx.x) >> 5;
    int lane = threadIdx.x & 31;
    if (gw >= NN) return;
    int n = gw;
    int beg = g_offs[n], end = g_offs[n + 1];
    float4 sd = *(const float4*)&g_sdst[n * 4];

    // pass A: per-head max (lane-strided over edges)
    float m0 = -1e30f, m1 = -1e30f, m2 = -1e30f, m3 = -1e30f;
    for (int j = beg + lane; j < end; j += 32) {
        int s = g_csr[j];
        float4 ss = *(const float4*)&g_ssrc[s * 4];
        m0 = fmaxf(m0, lrelu(ss.x + sd.x));
        m1 = fmaxf(m1, lrelu(ss.y + sd.y));
        m2 = fmaxf(m2, lrelu(ss.z + sd.z));
        m3 = fmaxf(m3, lrelu(ss.w + sd.w));
    }
#pragma unroll
    for (int off = 16; off; off >>= 1) {
        m0 = fmaxf(m0, __shfl_xor_sync(0xFFFFFFFFu, m0, off));
        m1 = fmaxf(m1, __shfl_xor_sync(0xFFFFFFFFu, m1, off));
        m2 = fmaxf(m2, __shfl_xor_sync(0xFFFFFFFFu, m2, off));
        m3 = fmaxf(m3, __shfl_xor_sync(0xFFFFFFFFu, m3, off));
    }

    int hsel = lane >> 3;   // my head
    float msel = hsel == 0 ? m0 : hsel == 1 ? m1 : hsel == 2 ? m2 : m3;

    // pass B+C fused: unnormalized weighted sums + denominators + hop-1 x gather
    float ha[8];
#pragma unroll
    for (int i = 0; i < 8; i++) ha[i] = 0.f;
    float den0 = 0.f, den1 = 0.f, den2 = 0.f, den3 = 0.f;
    float xa0 = 0.f, xa1 = 0.f;
    float densel = 0.f;

    for (int j = beg; j < end; j++) {
        int s = g_csr[j];
        float4 ss = *(const float4*)&g_ssrc[s * 4];   // lane-uniform broadcast
        float w0 = __expf(lrelu(ss.x + sd.x) - m0);
        float w1 = __expf(lrelu(ss.y + sd.y) - m1);
        float w2 = __expf(lrelu(ss.z + sd.z) - m2);
        float w3 = __expf(lrelu(ss.w + sd.w) - m3);
        den0 += w0; den1 += w1; den2 += w2; den3 += w3;
        float wsel = hsel == 0 ? w0 : hsel == 1 ? w1 : hsel == 2 ? w2 : w3;
        densel += wsel;
        // h row: 512B, lane takes 16B (8 halves, all same head)
        const uint4* hr = (const uint4*)(g_h + (size_t)s * 256);
        uint4 hv = hr[lane];
        float2 f0 = __half22float2(*(const __half2*)&hv.x);
        float2 f1 = __half22float2(*(const __half2*)&hv.y);
        float2 f2 = __half22float2(*(const __half2*)&hv.z);
        float2 f3 = __half22float2(*(const __half2*)&hv.w);
        ha[0] += wsel * f0.x; ha[1] += wsel * f0.y;
        ha[2] += wsel * f1.x; ha[3] += wsel * f1.y;
        ha[4] += wsel * f2.x; ha[5] += wsel * f2.y;
        ha[6] += wsel * f3.x; ha[7] += wsel * f3.y;
        // x row (fp16): 128B, lane takes 4B (2 halves)
        const unsigned int* xr = (const unsigned int*)(g_xh + (size_t)s * 64);
        unsigned int xv = xr[lane];
        float2 xf = __half22float2(*(const __half2*)&xv);
        xa0 += xf.x; xa1 += xf.y;
    }
    (void)den0; (void)den1; (void)den2; (void)den3;

    // normalize my head, then sum over heads (lanes differing in bits 3,4)
    float isel = 1.f / fmaxf(densel, 1e-16f);
#pragma unroll
    for (int i = 0; i < 8; i++) {
        float v = ha[i] * isel;
        v += __shfl_xor_sync(0xFFFFFFFFu, v, 8);
        v += __shfl_xor_sync(0xFFFFFFFFu, v, 16);
        ha[i] = 0.25f * v;
    }
    // lanes 0..7 hold cols [8*lane, 8*lane+8)
    if (lane < 8) {
        float4* dst = (float4*)(g_local + (size_t)n * 64 + 8 * lane);
        dst[0] = make_float4(ha[0], ha[1], ha[2], ha[3]);
        dst[1] = make_float4(ha[4], ha[5], ha[6], ha[7]);
    }
    // hop-1 output (fp16)
    float invd = 1.f / fmaxf((float)(end - beg), 1.f);
    __half2* g1 = (__half2*)(g_g1h + (size_t)n * 64);
    g1[lane] = __floats2half2_rn(xa0 * invd, xa1 * invd);
}

// ---------------- 6: hop-2 (fp16 gather, fp32 out) ----------------
__global__ void __launch_bounds__(256) k_glob2() {
    int gw = (blockIdx.x * blockDim.x + threadIdx.x) >> 5;
    int lane = threadIdx.x & 31;
    if (gw >= NN) return;
    int n = gw;
    int beg = g_offs[n], end = g_offs[n + 1];
    float a0 = 0.f, a1 = 0.f;
    for (int j = beg; j < end; j++) {
        int s = g_csr[j];
        const unsigned int* r = (const unsigned int*)(g_g1h + (size_t)s * 64);
        unsigned int v = r[lane];
        float2 f = __half22float2(*(const __half2*)&v);
        a0 += f.x; a1 += f.y;
    }
    float inv = 1.f / fmaxf((float)(end - beg), 1.f);
    float2* dst = (float2*)(g_g2 + (size_t)n * 64 + 2 * lane);
    *dst = make_float2(a0 * inv, a1 * inv);
}

// ---------------- 7: fold W_g into W_w lower half ----------------
__global__ void k_wg(const float* __restrict__ W_g, const float* __restrict__ b_g,
                     const float* __restrict__ W_w, const float* __restrict__ b_w) {
    int i0 = blockIdx.x * blockDim.x + threadIdx.x;
    int st = gridDim.x * blockDim.x;
    for (int idx = i0; idx < 4096; idx += st) {
        int i = idx >> 6, o = idx & 63;
        float s = 0.f;
        for (int k = 0; k < 64; k++)
            s += W_g[i * 64 + k] * W_w[(64 + k) * 64 + o];
        g_W2[idx] = s;
    }
    for (int o = i0; o < 64; o += st) {
        float s = b_w[o];
        for (int k = 0; k < 64; k++)
            s += b_g[k] * W_w[(64 + k) * 64 + o];
        g_b2[o] = s;
    }
}

// ---------------- 8: final projection out = local@W1 + g2@W2 + b2 ----------------
#define FIN_NPB 64
__global__ void __launch_bounds__(256) k_final(const float* __restrict__ W_w,
                                               float* __restrict__ out) {
    __shared__ float W1s[4096];
    __shared__ float W2s[4096];
    __shared__ float bs[64];
    __shared__ float ls[4][64];
    __shared__ float gs[4][64];
    int tid = threadIdx.x;
    for (int i = tid; i < 4096; i += 256) {
        W1s[i] = W_w[i];
        W2s[i] = g_W2[i];
    }
    if (tid < 64) bs[tid] = g_b2[tid];
    __syncthreads();

    int node0 = blockIdx.x * FIN_NPB;
    for (int nb = 0; nb < FIN_NPB; nb += 4) {
        __syncthreads();
        {
            int nn = node0 + nb + (tid >> 6);
            int c = tid & 63;
            if (nn < NN) {
                ls[tid >> 6][c] = g_local[(size_t)nn * 64 + c];
                gs[tid >> 6][c] = g_g2[(size_t)nn * 64 + c];
            }
        }
        __syncthreads();
        int nn = node0 + nb + (tid >> 6);
        if (nn < NN) {
            int o = tid & 63;
            float acc = bs[o];
            const float4* lr = (const float4*)ls[tid >> 6];
            const float4* gr = (const float4*)gs[tid >> 6];
#pragma unroll
            for (int kk = 0; kk < 16; kk++) {
                float4 lv = lr[kk];
                float4 gv = gr[kk];
                acc += lv.x * W1s[(kk * 4 + 0) * 64 + o] + gv.x * W2s[(kk * 4 + 0) * 64 + o];
                acc += lv.y * W1s[(kk * 4 + 1) * 64 + o] + gv.y * W2s[(kk * 4 + 1) * 64 + o];
                acc += lv.z * W1s[(kk * 4 + 2) * 64 + o] + gv.z * W2s[(kk * 4 + 2) * 64 + o];
                acc += lv.w * W1s[(kk * 4 + 3) * 64 + o] + gv.w * W2s[(kk * 4 + 3) * 64 + o];
            }
            out[(size_t)nn * 64 + o] = acc;
        }
    }
}

// ---------------- launch ----------------
extern "C" void kernel_launch(void* const* d_in, const int* in_sizes, int n_in,
                              void* d_out, int out_size) {
    const float* x     = (const float*)d_in[0];
    const void*  ei    = d_in[1];
    const float* W_att = (const float*)d_in[2];
    const float* a_src = (const float*)d_in[3];
    const float* a_dst = (const float*)d_in[4];
    const float* W_g   = (const float*)d_in[5];
    const float* b_g   = (const float*)d_in[6];
    const float* W_w   = (const float*)d_in[7];
    const float* b_w   = (const float*)d_in[8];
    float* out = (float*)d_out;

    k_detect<<<1, 256>>>((const unsigned int*)ei);
    k_init<<<256, 256>>>(x);
    k_hist<<<3125, 256>>>(ei);
    k_scan_a<<<SCAN_BLKS, 1024>>>();
    k_scan_b<<<1, 128>>>();
    k_scan_c<<<SCAN_BLKS, 1024>>>();
    k_scatter<<<3125, 256>>>(ei);
    k_feat<<<(NN + FEAT_NPB - 1) / FEAT_NPB, 128>>>(x, W_att, a_src, a_dst);
    k_attn<<<(NN * 32 + 255) / 256, 256>>>();
    k_glob2<<<(NN * 32 + 255) / 256, 256>>>();
    k_wg<<<17, 256>>>(W_g, b_g, W_w, b_w);
    k_final<<<(NN + FIN_NPB - 1) / FIN_NPB, 256>>>(W_w, out);
}